// round 10
// baseline (speedup 1.0000x reference)
#include <cuda_runtime.h>
#include <math.h>

#define Bq 4
#define Nq 2048
#define Kq 48
#define EC 128
#define TR 4  // rows per KNN block

// Scratch: gathered/masked token center coords, [B*N] as float4
__device__ float4 g_X[Bq * Nq];
// Precomputed positional-encoding contribution: C[d][c] for d in [0,65]
__device__ float g_C[66 * EC];

// ---------------------------------------------------------------------------
// Kernel 0: fold (one_hot(d) @ pe_w + pe_b) @ edge_w[0:16] into a 66x128 LUT
// ---------------------------------------------------------------------------
__global__ void prep_c_kernel(const float* __restrict__ pe_w,
                              const float* __restrict__ pe_b,
                              const float* __restrict__ edge_w) {
    int d = blockIdx.x;
    int c = threadIdx.x;
    float acc = 0.f;
#pragma unroll
    for (int t = 0; t < 16; t++)
        acc += (pe_w[d * 16 + t] + pe_b[t]) * edge_w[t * EC + c];
    g_C[d * EC + c] = acc;
}

// ---------------------------------------------------------------------------
// Kernel 1: gather center-atom coords, apply token mask
// ---------------------------------------------------------------------------
__global__ void gather_x_kernel(const float* __restrict__ coords,
                                const float* __restrict__ mask,
                                const int* __restrict__ center) {
    int t = blockIdx.x * blockDim.x + threadIdx.x;
    if (t >= Bq * Nq) return;
    int b = t / Nq;
    int c = center[t];
    float m = mask[t];
    const float* p = coords + ((size_t)b * Nq + c) * 3;
    g_X[t] = make_float4(p[0] * m, p[1] * m, p[2] * m, 0.f);
}

// ---------------------------------------------------------------------------
// Kernel 2: masked top-K, squared-distance domain, 4 ROWS PER BLOCK.
// All serial phases (barriers, scans) are amortized across 4 rows; the
// per-round digit scan runs warps 0-3 in parallel (one row each).
// Algorithm identical to the passing single-row version: 4 radix rounds over
// the 32 s-bits + bitmap index tie-break + post-sqrt (D, j) rerank of the 48.
// ---------------------------------------------------------------------------
__global__ __launch_bounds__(256) void knn_kernel(const float* __restrict__ mask,
                                                  float* __restrict__ outIdx,
                                                  float* __restrict__ outD) {
    __shared__ float Dsm[TR][Nq];              // squared (adjusted) distances
    __shared__ unsigned hist[TR][256];
    __shared__ float warpred[8][TR];
    __shared__ float s_smax[TR];
    __shared__ unsigned s_prefix[TR];
    __shared__ int s_rank[TR];
    __shared__ int s_cnt[TR];
    __shared__ unsigned long long cand[TR][Kq];
    __shared__ unsigned tiebm[TR][64];
    __shared__ unsigned tiepfx[TR][64];

    int blk = blockIdx.x;
    int row0 = blk * TR;
    int b = row0 / Nq;
    int tid = threadIdx.x;
    int lane = tid & 31, warp = tid >> 5;

    float4 xi[TR];
    float mi[TR];
#pragma unroll
    for (int r = 0; r < TR; r++) { xi[r] = g_X[row0 + r]; mi[r] = mask[row0 + r]; }
    const float* mrow = mask + b * Nq;

    // Pass 1: squared distances for 4 rows per xj load + masked row maxima
    float lmax[TR] = {0.f, 0.f, 0.f, 0.f};
#pragma unroll
    for (int q = 0; q < Nq / 256; q++) {
        int j = tid + q * 256;
        float4 xj = g_X[b * Nq + j];
        float mj = mrow[j];
#pragma unroll
        for (int r = 0; r < TR; r++) {
            float dx = xi[r].x - xj.x, dy = xi[r].y - xj.y, dz = xi[r].z - xj.z;
            float s = dx * dx + dy * dy + dz * dz + 1e-6f;
            Dsm[r][j] = s;
            lmax[r] = fmaxf(lmax[r], (mi[r] * mj != 0.f) ? s : 0.f);
        }
    }
#pragma unroll
    for (int r = 0; r < TR; r++)
        for (int o = 16; o; o >>= 1)
            lmax[r] = fmaxf(lmax[r], __shfl_xor_sync(~0u, lmax[r], o));
    if (lane == 0)
#pragma unroll
        for (int r = 0; r < TR; r++) warpred[warp][r] = lmax[r];
    __syncthreads();
    if (tid < TR) {
        float m = warpred[0][tid];
#pragma unroll
        for (int w = 1; w < 8; w++) m = fmaxf(m, warpred[w][tid]);
        s_smax[tid] = m;
        s_rank[tid] = Kq;
        s_cnt[tid] = 0;
        s_prefix[tid] = 0;
    }
    ((unsigned*)tiebm)[tid] = 0;  // TR*64 = 256 words
    __syncthreads();

    // Masked-adjust pass: masked pairs -> smax (s-domain Dmax). No-op when
    // the mask is all ones (conditional write only).
    {
        float smaxr[TR];
#pragma unroll
        for (int r = 0; r < TR; r++) smaxr[r] = s_smax[r];
#pragma unroll
        for (int q = 0; q < Nq / 256; q++) {
            int j = tid + q * 256;
            float mj = mrow[j];
#pragma unroll
            for (int r = 0; r < TR; r++)
                if (mi[r] * mj == 0.f) Dsm[r][j] = smaxr[r];
        }
    }
    __syncthreads();

    // 4 radix rounds over the 32 squared-distance bits (8-bit digits).
    unsigned pmask = 0;
#pragma unroll 1
    for (int rd = 0; rd < 4; rd++) {
        int sh = 24 - rd * 8;
#pragma unroll
        for (int h = 0; h < TR; h++) ((unsigned*)hist)[tid + h * 256] = 0;
        __syncthreads();
#pragma unroll
        for (int r = 0; r < TR; r++) {
            unsigned pr = s_prefix[r];
#pragma unroll
            for (int q = 0; q < Nq / 256; q++) {
                unsigned u = __float_as_uint(Dsm[r][tid + q * 256]);
                if ((u & pmask) == pr) atomicAdd(&hist[r][(u >> sh) & 255u], 1u);
            }
        }
        __syncthreads();
        if (warp < TR) {  // warp r scans row r's 256 bins
            int r = warp;
            int base = lane * 8;
            unsigned cnts[8];
            unsigned p = 0;
#pragma unroll
            for (int q2 = 0; q2 < 8; q2++) { cnts[q2] = hist[r][base + q2]; p += cnts[q2]; }
            unsigned incl = p;
            for (int o = 1; o < 32; o <<= 1) {
                unsigned v = __shfl_up_sync(~0u, incl, o);
                if (lane >= o) incl += v;
            }
            unsigned excl = incl - p;
            int rk = s_rank[r];
            __syncwarp();
            if ((int)excl < rk && rk <= (int)incl) {
                int rr = rk - (int)excl;
#pragma unroll
                for (int q2 = 0; q2 < 8; q2++) {
                    if (rr <= (int)cnts[q2]) {
                        s_prefix[r] |= (unsigned)(base + q2) << sh;
                        s_rank[r] = rr;
                        break;
                    }
                    rr -= (int)cnts[q2];
                }
            }
        }
        __syncthreads();
        pmask |= 0xFFu << sh;
    }

    // Gather: keys with s < distpre selected outright; s == distpre marked in
    // the per-row bitmap for index tie-break.
    unsigned distpre[TR];
    int quota[TR];
#pragma unroll
    for (int r = 0; r < TR; r++) { distpre[r] = s_prefix[r]; quota[r] = s_rank[r]; }
#pragma unroll
    for (int r = 0; r < TR; r++) {
#pragma unroll
        for (int q = 0; q < Nq / 256; q++) {
            int j = tid + q * 256;
            unsigned u = __float_as_uint(Dsm[r][j]);
            if (u < distpre[r]) {
                int pos = atomicAdd(&s_cnt[r], 1);
                cand[r][pos] = ((unsigned long long)u << 32) | (unsigned)j;
            } else if (u == distpre[r]) {
                atomicOr(&tiebm[r][j >> 5], 1u << (j & 31));
            }
        }
    }
    __syncthreads();
    if (tid < TR) {
        unsigned acc = 0;
#pragma unroll 1
        for (int w = 0; w < 64; w++) { tiepfx[tid][w] = acc; acc += __popc(tiebm[tid][w]); }
    }
    __syncthreads();
#pragma unroll
    for (int r = 0; r < TR; r++) {
#pragma unroll
        for (int q = 0; q < Nq / 256; q++) {
            int j = tid + q * 256;
            unsigned u = __float_as_uint(Dsm[r][j]);
            if (u == distpre[r]) {
                int rk = (int)tiepfx[r][j >> 5] +
                         __popc(tiebm[r][j >> 5] & ((1u << (j & 31)) - 1u));
                if (rk < quota[r]) {
                    int pos = atomicAdd(&s_cnt[r], 1);
                    if (pos < Kq) cand[r][pos] = ((unsigned long long)u << 32) | (unsigned)j;
                }
            }
        }
    }
    __syncthreads();
    // sqrt only the selected; rerank on (D_bits, j) = reference post-sqrt order
    if (tid < TR * Kq) {
        int r = tid / Kq, k = tid % Kq;
        unsigned long long key = cand[r][k];
        float D = sqrtf(__uint_as_float((unsigned)(key >> 32)));
        cand[r][k] = ((unsigned long long)__float_as_uint(D) << 32) |
                     (key & 0xFFFFFFFFull);
    }
    __syncthreads();
    if (tid < TR * Kq) {
        int r = tid / Kq, k = tid % Kq;
        unsigned long long key = cand[r][k];
        int rk = 0;
#pragma unroll
        for (int s = 0; s < Kq; s++) rk += (cand[r][s] < key);
        int j = (int)(unsigned)(key & 0xFFFFFFFFull);
        outIdx[(size_t)(row0 + r) * Kq + rk] = (float)j;
        outD[(size_t)(row0 + r) * Kq + rk] = __uint_as_float((unsigned)(key >> 32));
    }
}

// ---------------------------------------------------------------------------
// Kernel 3: per-edge features -> output channels + LayerNorm.
// 64 threads per (b,i); thread owns ADJACENT channel pair (2c, 2c+1).
// (R5 version, unchanged.)
// ---------------------------------------------------------------------------
__global__ __launch_bounds__(64) void edge_kernel(
    const float* __restrict__ eidx, const float* __restrict__ dnb,
    const int* __restrict__ resi, const int* __restrict__ lig,
    const float* __restrict__ bonds,
    const float* __restrict__ edge_w,
    const float* __restrict__ ln_g, const float* __restrict__ ln_b,
    float* __restrict__ outE) {
    __shared__ __align__(16) float f[Kq][20];  // 16 rbf + tb + pad
    __shared__ int dsm[Kq];
    __shared__ float red[8][2][2];
    __shared__ float stats[8][2];

    int c = threadIdx.x;  // 0..63 -> channels (2c, 2c+1)
    int lane = c & 31, warp = c >> 5;
    int row = blockIdx.x;
    int b = row / Nq, i = row % Nq;

    float2 w[17];
#pragma unroll
    for (int t = 0; t < 16; t++)
        w[t] = *(const float2*)&edge_w[(16 + t) * EC + 2 * c];
    w[16] = *(const float2*)&edge_w[32 * EC + 2 * c];
    float2 gg = *(const float2*)&ln_g[2 * c];
    float2 bb = *(const float2*)&ln_b[2 * c];

    int ri = resi[row];
    int li = lig[row];
    const float* brow = bonds + ((size_t)b * Nq + i) * Nq;

    if (c < Kq) {
        int k = c;
        int j = (int)eidx[(size_t)row * Kq + k];
        float dk = dnb[(size_t)row * Kq + k];
        // chain_labels all-zero in reference => E_chains == 1 always
        int d = ri - resi[b * Nq + j] + 32;
        dsm[k] = max(0, min(64, d));
#pragma unroll
        for (int m = 0; m < 16; m++) {
            float mu = 2.f + (20.f / 15.f) * (float)m;
            float x = (dk - mu) * 0.8f;  // 1/1.25
            f[k][m] = __expf(-x * x);
        }
        f[k][16] = (li | lig[b * Nq + j]) ? brow[j] : 0.f;
        f[k][17] = f[k][18] = f[k][19] = 0.f;
    }
    __syncthreads();

#pragma unroll 1
    for (int k0 = 0; k0 < Kq; k0 += 8) {
        float2 e[8];
#pragma unroll
        for (int kk = 0; kk < 8; kk++) {
            const float4* fp = (const float4*)f[k0 + kk];
            float2 C = *(const float2*)&g_C[dsm[k0 + kk] * EC + 2 * c];
            float a0 = C.x, a1 = C.y;
#pragma unroll
            for (int q = 0; q < 4; q++) {
                float4 v = fp[q];
                a0 += v.x * w[4 * q].x + v.y * w[4 * q + 1].x +
                      v.z * w[4 * q + 2].x + v.w * w[4 * q + 3].x;
                a1 += v.x * w[4 * q].y + v.y * w[4 * q + 1].y +
                      v.z * w[4 * q + 2].y + v.w * w[4 * q + 3].y;
            }
            float tb = fp[4].x;
            a0 += tb * w[16].x;
            a1 += tb * w[16].y;
            e[kk] = make_float2(a0, a1);
        }
#pragma unroll
        for (int kk = 0; kk < 8; kk++) {
            float s = e[kk].x + e[kk].y;
            float s2 = e[kk].x * e[kk].x + e[kk].y * e[kk].y;
            for (int o = 16; o; o >>= 1) {
                s += __shfl_xor_sync(~0u, s, o);
                s2 += __shfl_xor_sync(~0u, s2, o);
            }
            if (lane == 0) { red[kk][warp][0] = s; red[kk][warp][1] = s2; }
        }
        __syncthreads();
        if (c < 8) {
            float s = red[c][0][0] + red[c][1][0];
            float s2 = red[c][0][1] + red[c][1][1];
            float mean = s * (1.f / EC);
            float var = s2 * (1.f / EC) - mean * mean;
            stats[c][0] = mean;
            stats[c][1] = rsqrtf(var + 1e-5f);
        }
        __syncthreads();
        size_t baseo = ((size_t)row * Kq + k0) * EC + 2 * c;
#pragma unroll
        for (int kk = 0; kk < 8; kk++) {
            float mean = stats[kk][0], rstd = stats[kk][1];
            float2 o2;
            o2.x = (e[kk].x - mean) * rstd * gg.x + bb.x;
            o2.y = (e[kk].y - mean) * rstd * gg.y + bb.y;
            *(float2*)&outE[baseo + (size_t)kk * EC] = o2;
        }
        __syncthreads();
    }
}

// ---------------------------------------------------------------------------
extern "C" void kernel_launch(void* const* d_in, const int* in_sizes, int n_in,
                              void* d_out, int out_size) {
    const float* coords = (const float*)d_in[0];
    const float* mask   = (const float*)d_in[1];
    const float* bonds  = (const float*)d_in[2];
    const float* pe_w   = (const float*)d_in[3];
    const float* pe_b   = (const float*)d_in[4];
    const float* edge_w = (const float*)d_in[5];
    const float* ln_g   = (const float*)d_in[6];
    const float* ln_b   = (const float*)d_in[7];
    const int* center   = (const int*)d_in[8];
    const int* resi     = (const int*)d_in[9];
    // d_in[10] = asym_id (unused: chain encoding disabled in reference)
    const int* lig      = (const int*)d_in[11];

    float* outE = (float*)d_out;
    size_t nE = (size_t)Bq * Nq * Kq * EC;        // 50,331,648
    float* outIdx = outE + nE;                    // E_idx as float
    float* outD = outIdx + (size_t)Bq * Nq * Kq;  // D_neighbors

    prep_c_kernel<<<66, 128>>>(pe_w, pe_b, edge_w);
    gather_x_kernel<<<(Bq * Nq + 255) / 256, 256>>>(coords, mask, center);
    knn_kernel<<<Bq * Nq / TR, 256>>>(mask, outIdx, outD);
    edge_kernel<<<Bq * Nq, 64>>>(outIdx, outD, resi, lig, bonds, edge_w,
                                 ln_g, ln_b, outE);
}

// round 11
// speedup vs baseline: 1.6864x; 1.6864x over previous
#include <cuda_runtime.h>
#include <math.h>

#define Bq 4
#define Nq 2048
#define Kq 48
#define EC 128
#define TR 4  // rows per KNN block

// Scratch: gathered/masked token center coords, [B*N] as float4
__device__ float4 g_X[Bq * Nq];
// Precomputed positional-encoding contribution: C[d][c] for d in [0,65]
__device__ float g_C[66 * EC];

// ---------------------------------------------------------------------------
// Kernel 0: fold (one_hot(d) @ pe_w + pe_b) @ edge_w[0:16] into a 66x128 LUT
// ---------------------------------------------------------------------------
__global__ void prep_c_kernel(const float* __restrict__ pe_w,
                              const float* __restrict__ pe_b,
                              const float* __restrict__ edge_w) {
    int d = blockIdx.x;
    int c = threadIdx.x;
    float acc = 0.f;
#pragma unroll
    for (int t = 0; t < 16; t++)
        acc += (pe_w[d * 16 + t] + pe_b[t]) * edge_w[t * EC + c];
    g_C[d * EC + c] = acc;
}

// ---------------------------------------------------------------------------
// Kernel 1: gather center-atom coords, apply token mask
// ---------------------------------------------------------------------------
__global__ void gather_x_kernel(const float* __restrict__ coords,
                                const float* __restrict__ mask,
                                const int* __restrict__ center) {
    int t = blockIdx.x * blockDim.x + threadIdx.x;
    if (t >= Bq * Nq) return;
    int b = t / Nq;
    int c = center[t];
    float m = mask[t];
    const float* p = coords + ((size_t)b * Nq + c) * 3;
    g_X[t] = make_float4(p[0] * m, p[1] * m, p[2] * m, 0.f);
}

// ---------------------------------------------------------------------------
// Kernel 2: masked top-K, squared-distance domain, 4 ROWS PER BLOCK.
// (R10 version, unchanged -- normalized evidence shows it beats 1-row.)
// ---------------------------------------------------------------------------
__global__ __launch_bounds__(256) void knn_kernel(const float* __restrict__ mask,
                                                  float* __restrict__ outIdx,
                                                  float* __restrict__ outD) {
    __shared__ float Dsm[TR][Nq];              // squared (adjusted) distances
    __shared__ unsigned hist[TR][256];
    __shared__ float warpred[8][TR];
    __shared__ float s_smax[TR];
    __shared__ unsigned s_prefix[TR];
    __shared__ int s_rank[TR];
    __shared__ int s_cnt[TR];
    __shared__ unsigned long long cand[TR][Kq];
    __shared__ unsigned tiebm[TR][64];
    __shared__ unsigned tiepfx[TR][64];

    int blk = blockIdx.x;
    int row0 = blk * TR;
    int b = row0 / Nq;
    int tid = threadIdx.x;
    int lane = tid & 31, warp = tid >> 5;

    float4 xi[TR];
    float mi[TR];
#pragma unroll
    for (int r = 0; r < TR; r++) { xi[r] = g_X[row0 + r]; mi[r] = mask[row0 + r]; }
    const float* mrow = mask + b * Nq;

    // Pass 1: squared distances for 4 rows per xj load + masked row maxima
    float lmax[TR] = {0.f, 0.f, 0.f, 0.f};
#pragma unroll
    for (int q = 0; q < Nq / 256; q++) {
        int j = tid + q * 256;
        float4 xj = g_X[b * Nq + j];
        float mj = mrow[j];
#pragma unroll
        for (int r = 0; r < TR; r++) {
            float dx = xi[r].x - xj.x, dy = xi[r].y - xj.y, dz = xi[r].z - xj.z;
            float s = dx * dx + dy * dy + dz * dz + 1e-6f;
            Dsm[r][j] = s;
            lmax[r] = fmaxf(lmax[r], (mi[r] * mj != 0.f) ? s : 0.f);
        }
    }
#pragma unroll
    for (int r = 0; r < TR; r++)
        for (int o = 16; o; o >>= 1)
            lmax[r] = fmaxf(lmax[r], __shfl_xor_sync(~0u, lmax[r], o));
    if (lane == 0)
#pragma unroll
        for (int r = 0; r < TR; r++) warpred[warp][r] = lmax[r];
    __syncthreads();
    if (tid < TR) {
        float m = warpred[0][tid];
#pragma unroll
        for (int w = 1; w < 8; w++) m = fmaxf(m, warpred[w][tid]);
        s_smax[tid] = m;
        s_rank[tid] = Kq;
        s_cnt[tid] = 0;
        s_prefix[tid] = 0;
    }
    ((unsigned*)tiebm)[tid] = 0;  // TR*64 = 256 words
    __syncthreads();

    // Masked-adjust pass: masked pairs -> smax (s-domain Dmax).
    {
        float smaxr[TR];
#pragma unroll
        for (int r = 0; r < TR; r++) smaxr[r] = s_smax[r];
#pragma unroll
        for (int q = 0; q < Nq / 256; q++) {
            int j = tid + q * 256;
            float mj = mrow[j];
#pragma unroll
            for (int r = 0; r < TR; r++)
                if (mi[r] * mj == 0.f) Dsm[r][j] = smaxr[r];
        }
    }
    __syncthreads();

    // 4 radix rounds over the 32 squared-distance bits (8-bit digits).
    unsigned pmask = 0;
#pragma unroll 1
    for (int rd = 0; rd < 4; rd++) {
        int sh = 24 - rd * 8;
#pragma unroll
        for (int h = 0; h < TR; h++) ((unsigned*)hist)[tid + h * 256] = 0;
        __syncthreads();
#pragma unroll
        for (int r = 0; r < TR; r++) {
            unsigned pr = s_prefix[r];
#pragma unroll
            for (int q = 0; q < Nq / 256; q++) {
                unsigned u = __float_as_uint(Dsm[r][tid + q * 256]);
                if ((u & pmask) == pr) atomicAdd(&hist[r][(u >> sh) & 255u], 1u);
            }
        }
        __syncthreads();
        if (warp < TR) {  // warp r scans row r's 256 bins
            int r = warp;
            int base = lane * 8;
            unsigned cnts[8];
            unsigned p = 0;
#pragma unroll
            for (int q2 = 0; q2 < 8; q2++) { cnts[q2] = hist[r][base + q2]; p += cnts[q2]; }
            unsigned incl = p;
            for (int o = 1; o < 32; o <<= 1) {
                unsigned v = __shfl_up_sync(~0u, incl, o);
                if (lane >= o) incl += v;
            }
            unsigned excl = incl - p;
            int rk = s_rank[r];
            __syncwarp();
            if ((int)excl < rk && rk <= (int)incl) {
                int rr = rk - (int)excl;
#pragma unroll
                for (int q2 = 0; q2 < 8; q2++) {
                    if (rr <= (int)cnts[q2]) {
                        s_prefix[r] |= (unsigned)(base + q2) << sh;
                        s_rank[r] = rr;
                        break;
                    }
                    rr -= (int)cnts[q2];
                }
            }
        }
        __syncthreads();
        pmask |= 0xFFu << sh;
    }

    // Gather: keys with s < distpre selected outright; s == distpre marked in
    // the per-row bitmap for index tie-break.
    unsigned distpre[TR];
    int quota[TR];
#pragma unroll
    for (int r = 0; r < TR; r++) { distpre[r] = s_prefix[r]; quota[r] = s_rank[r]; }
#pragma unroll
    for (int r = 0; r < TR; r++) {
#pragma unroll
        for (int q = 0; q < Nq / 256; q++) {
            int j = tid + q * 256;
            unsigned u = __float_as_uint(Dsm[r][j]);
            if (u < distpre[r]) {
                int pos = atomicAdd(&s_cnt[r], 1);
                cand[r][pos] = ((unsigned long long)u << 32) | (unsigned)j;
            } else if (u == distpre[r]) {
                atomicOr(&tiebm[r][j >> 5], 1u << (j & 31));
            }
        }
    }
    __syncthreads();
    if (tid < TR) {
        unsigned acc = 0;
#pragma unroll 1
        for (int w = 0; w < 64; w++) { tiepfx[tid][w] = acc; acc += __popc(tiebm[tid][w]); }
    }
    __syncthreads();
#pragma unroll
    for (int r = 0; r < TR; r++) {
#pragma unroll
        for (int q = 0; q < Nq / 256; q++) {
            int j = tid + q * 256;
            unsigned u = __float_as_uint(Dsm[r][j]);
            if (u == distpre[r]) {
                int rk = (int)tiepfx[r][j >> 5] +
                         __popc(tiebm[r][j >> 5] & ((1u << (j & 31)) - 1u));
                if (rk < quota[r]) {
                    int pos = atomicAdd(&s_cnt[r], 1);
                    if (pos < Kq) cand[r][pos] = ((unsigned long long)u << 32) | (unsigned)j;
                }
            }
        }
    }
    __syncthreads();
    // sqrt only the selected; rerank on (D_bits, j) = reference post-sqrt order
    if (tid < TR * Kq) {
        int r = tid / Kq, k = tid % Kq;
        unsigned long long key = cand[r][k];
        float D = sqrtf(__uint_as_float((unsigned)(key >> 32)));
        cand[r][k] = ((unsigned long long)__float_as_uint(D) << 32) |
                     (key & 0xFFFFFFFFull);
    }
    __syncthreads();
    if (tid < TR * Kq) {
        int r = tid / Kq, k = tid % Kq;
        unsigned long long key = cand[r][k];
        int rk = 0;
#pragma unroll
        for (int s = 0; s < Kq; s++) rk += (cand[r][s] < key);
        int j = (int)(unsigned)(key & 0xFFFFFFFFull);
        outIdx[(size_t)(row0 + r) * Kq + rk] = (float)j;
        outD[(size_t)(row0 + r) * Kq + rk] = __uint_as_float((unsigned)(key >> 32));
    }
}

// ---------------------------------------------------------------------------
// Kernel 3: per-edge features -> output channels + LayerNorm.
// ONE WARP per (b,i); thread owns channels (4c..4c+3). LN is a pure
// shfl_xor reduction (no barriers, no smem stats). Halves broadcast-LDS and
// store wavefronts again vs the 64-thread version.
// ---------------------------------------------------------------------------
__global__ __launch_bounds__(32) void edge_kernel(
    const float* __restrict__ eidx, const float* __restrict__ dnb,
    const int* __restrict__ resi, const int* __restrict__ lig,
    const float* __restrict__ bonds,
    const float* __restrict__ edge_w,
    const float* __restrict__ ln_g, const float* __restrict__ ln_b,
    float* __restrict__ outE) {
    __shared__ __align__(16) float f[Kq][20];  // 16 rbf + tb + pad
    __shared__ int dsm[Kq];

    int lane = threadIdx.x;  // 0..31 -> channels (4*lane .. 4*lane+3)
    int row = blockIdx.x;
    int b = row / Nq, i = row % Nq;
    int c4 = 4 * lane;

    float4 w[17];
#pragma unroll
    for (int t = 0; t < 16; t++)
        w[t] = *(const float4*)&edge_w[(16 + t) * EC + c4];
    w[16] = *(const float4*)&edge_w[32 * EC + c4];
    float4 gg = *(const float4*)&ln_g[c4];
    float4 bb = *(const float4*)&ln_b[c4];

    int ri = resi[row];
    int li = lig[row];
    const float* brow = bonds + ((size_t)b * Nq + i) * Nq;

    // Build feature rows: 32 threads cover 48 edges
    for (int k = lane; k < Kq; k += 32) {
        int j = (int)eidx[(size_t)row * Kq + k];
        float dk = dnb[(size_t)row * Kq + k];
        // chain_labels all-zero in reference => E_chains == 1 always
        int d = ri - resi[b * Nq + j] + 32;
        dsm[k] = max(0, min(64, d));
#pragma unroll
        for (int m = 0; m < 16; m++) {
            float mu = 2.f + (20.f / 15.f) * (float)m;
            float x = (dk - mu) * 0.8f;  // 1/1.25
            f[k][m] = __expf(-x * x);
        }
        f[k][16] = (li | lig[b * Nq + j]) ? brow[j] : 0.f;
        f[k][17] = f[k][18] = f[k][19] = 0.f;
    }
    __syncwarp();

#pragma unroll 1
    for (int k = 0; k < Kq; k++) {
        const float4* fp = (const float4*)f[k];
        float4 C = *(const float4*)&g_C[dsm[k] * EC + c4];
        float a0 = C.x, a1 = C.y, a2 = C.z, a3 = C.w;
#pragma unroll
        for (int q = 0; q < 4; q++) {
            float4 v = fp[q];
            a0 += v.x * w[4 * q].x + v.y * w[4 * q + 1].x + v.z * w[4 * q + 2].x + v.w * w[4 * q + 3].x;
            a1 += v.x * w[4 * q].y + v.y * w[4 * q + 1].y + v.z * w[4 * q + 2].y + v.w * w[4 * q + 3].y;
            a2 += v.x * w[4 * q].z + v.y * w[4 * q + 1].z + v.z * w[4 * q + 2].z + v.w * w[4 * q + 3].z;
            a3 += v.x * w[4 * q].w + v.y * w[4 * q + 1].w + v.z * w[4 * q + 2].w + v.w * w[4 * q + 3].w;
        }
        float tb = fp[4].x;
        a0 += tb * w[16].x;
        a1 += tb * w[16].y;
        a2 += tb * w[16].z;
        a3 += tb * w[16].w;
        // LayerNorm across 128 channels: 4 per thread + warp shuffle reduce
        float s = a0 + a1 + a2 + a3;
        float s2 = a0 * a0 + a1 * a1 + a2 * a2 + a3 * a3;
#pragma unroll
        for (int o = 16; o; o >>= 1) {
            s += __shfl_xor_sync(~0u, s, o);
            s2 += __shfl_xor_sync(~0u, s2, o);
        }
        float mean = s * (1.f / EC);
        float var = s2 * (1.f / EC) - mean * mean;
        float rstd = rsqrtf(var + 1e-5f);
        float4 o4;
        o4.x = (a0 - mean) * rstd * gg.x + bb.x;
        o4.y = (a1 - mean) * rstd * gg.y + bb.y;
        o4.z = (a2 - mean) * rstd * gg.z + bb.z;
        o4.w = (a3 - mean) * rstd * gg.w + bb.w;
        *(float4*)&outE[((size_t)row * Kq + k) * EC + c4] = o4;
    }
}

// ---------------------------------------------------------------------------
extern "C" void kernel_launch(void* const* d_in, const int* in_sizes, int n_in,
                              void* d_out, int out_size) {
    const float* coords = (const float*)d_in[0];
    const float* mask   = (const float*)d_in[1];
    const float* bonds  = (const float*)d_in[2];
    const float* pe_w   = (const float*)d_in[3];
    const float* pe_b   = (const float*)d_in[4];
    const float* edge_w = (const float*)d_in[5];
    const float* ln_g   = (const float*)d_in[6];
    const float* ln_b   = (const float*)d_in[7];
    const int* center   = (const int*)d_in[8];
    const int* resi     = (const int*)d_in[9];
    // d_in[10] = asym_id (unused: chain encoding disabled in reference)
    const int* lig      = (const int*)d_in[11];

    float* outE = (float*)d_out;
    size_t nE = (size_t)Bq * Nq * Kq * EC;        // 50,331,648
    float* outIdx = outE + nE;                    // E_idx as float
    float* outD = outIdx + (size_t)Bq * Nq * Kq;  // D_neighbors

    prep_c_kernel<<<66, 128>>>(pe_w, pe_b, edge_w);
    gather_x_kernel<<<(Bq * Nq + 255) / 256, 256>>>(coords, mask, center);
    knn_kernel<<<Bq * Nq / TR, 256>>>(mask, outIdx, outD);
    edge_kernel<<<Bq * Nq, 32>>>(outIdx, outD, resi, lig, bonds, edge_w,
                                 ln_g, ln_b, outE);
}

// round 12
// speedup vs baseline: 1.7312x; 1.0266x over previous
#include <cuda_runtime.h>
#include <math.h>

#define Bq 4
#define Nq 2048
#define Kq 48
#define EC 128
#define TR 4  // rows per KNN block

// Scratch: gathered/masked token center coords, [B*N] as float4
__device__ float4 g_X[Bq * Nq];
// Precomputed positional-encoding contribution: C[d][c] for d in [0,65]
__device__ float g_C[66 * EC];

__device__ __forceinline__ unsigned long long pack2(float a, float b) {
    unsigned long long r;
    asm("mov.b64 %0, {%1, %2};" : "=l"(r) : "f"(a), "f"(b));
    return r;
}
__device__ __forceinline__ void unpack2(unsigned long long v, float& a, float& b) {
    asm("mov.b64 {%0, %1}, %2;" : "=f"(a), "=f"(b) : "l"(v));
}
__device__ __forceinline__ void fma2(unsigned long long& d, unsigned long long a,
                                     unsigned long long b) {
    asm("fma.rn.f32x2 %0, %1, %2, %3;" : "=l"(d) : "l"(a), "l"(b), "l"(d));
}

// ---------------------------------------------------------------------------
// Kernel 0: fold (one_hot(d) @ pe_w + pe_b) @ edge_w[0:16] into a 66x128 LUT
// ---------------------------------------------------------------------------
__global__ void prep_c_kernel(const float* __restrict__ pe_w,
                              const float* __restrict__ pe_b,
                              const float* __restrict__ edge_w) {
    int d = blockIdx.x;
    int c = threadIdx.x;
    float acc = 0.f;
#pragma unroll
    for (int t = 0; t < 16; t++)
        acc += (pe_w[d * 16 + t] + pe_b[t]) * edge_w[t * EC + c];
    g_C[d * EC + c] = acc;
}

// ---------------------------------------------------------------------------
// Kernel 1: gather center-atom coords, apply token mask
// ---------------------------------------------------------------------------
__global__ void gather_x_kernel(const float* __restrict__ coords,
                                const float* __restrict__ mask,
                                const int* __restrict__ center) {
    int t = blockIdx.x * blockDim.x + threadIdx.x;
    if (t >= Bq * Nq) return;
    int b = t / Nq;
    int c = center[t];
    float m = mask[t];
    const float* p = coords + ((size_t)b * Nq + c) * 3;
    g_X[t] = make_float4(p[0] * m, p[1] * m, p[2] * m, 0.f);
}

// ---------------------------------------------------------------------------
// Kernel 2: masked top-K, squared-distance domain, 4 ROWS PER BLOCK.
// (R10/R11 version, unchanged.)
// ---------------------------------------------------------------------------
__global__ __launch_bounds__(256) void knn_kernel(const float* __restrict__ mask,
                                                  float* __restrict__ outIdx,
                                                  float* __restrict__ outD) {
    __shared__ float Dsm[TR][Nq];              // squared (adjusted) distances
    __shared__ unsigned hist[TR][256];
    __shared__ float warpred[8][TR];
    __shared__ float s_smax[TR];
    __shared__ unsigned s_prefix[TR];
    __shared__ int s_rank[TR];
    __shared__ int s_cnt[TR];
    __shared__ unsigned long long cand[TR][Kq];
    __shared__ unsigned tiebm[TR][64];
    __shared__ unsigned tiepfx[TR][64];

    int blk = blockIdx.x;
    int row0 = blk * TR;
    int b = row0 / Nq;
    int tid = threadIdx.x;
    int lane = tid & 31, warp = tid >> 5;

    float4 xi[TR];
    float mi[TR];
#pragma unroll
    for (int r = 0; r < TR; r++) { xi[r] = g_X[row0 + r]; mi[r] = mask[row0 + r]; }
    const float* mrow = mask + b * Nq;

    // Pass 1: squared distances for 4 rows per xj load + masked row maxima
    float lmax[TR] = {0.f, 0.f, 0.f, 0.f};
#pragma unroll
    for (int q = 0; q < Nq / 256; q++) {
        int j = tid + q * 256;
        float4 xj = g_X[b * Nq + j];
        float mj = mrow[j];
#pragma unroll
        for (int r = 0; r < TR; r++) {
            float dx = xi[r].x - xj.x, dy = xi[r].y - xj.y, dz = xi[r].z - xj.z;
            float s = dx * dx + dy * dy + dz * dz + 1e-6f;
            Dsm[r][j] = s;
            lmax[r] = fmaxf(lmax[r], (mi[r] * mj != 0.f) ? s : 0.f);
        }
    }
#pragma unroll
    for (int r = 0; r < TR; r++)
        for (int o = 16; o; o >>= 1)
            lmax[r] = fmaxf(lmax[r], __shfl_xor_sync(~0u, lmax[r], o));
    if (lane == 0)
#pragma unroll
        for (int r = 0; r < TR; r++) warpred[warp][r] = lmax[r];
    __syncthreads();
    if (tid < TR) {
        float m = warpred[0][tid];
#pragma unroll
        for (int w = 1; w < 8; w++) m = fmaxf(m, warpred[w][tid]);
        s_smax[tid] = m;
        s_rank[tid] = Kq;
        s_cnt[tid] = 0;
        s_prefix[tid] = 0;
    }
    ((unsigned*)tiebm)[tid] = 0;  // TR*64 = 256 words
    __syncthreads();

    // Masked-adjust pass: masked pairs -> smax (s-domain Dmax).
    {
        float smaxr[TR];
#pragma unroll
        for (int r = 0; r < TR; r++) smaxr[r] = s_smax[r];
#pragma unroll
        for (int q = 0; q < Nq / 256; q++) {
            int j = tid + q * 256;
            float mj = mrow[j];
#pragma unroll
            for (int r = 0; r < TR; r++)
                if (mi[r] * mj == 0.f) Dsm[r][j] = smaxr[r];
        }
    }
    __syncthreads();

    // 4 radix rounds over the 32 squared-distance bits (8-bit digits).
    unsigned pmask = 0;
#pragma unroll 1
    for (int rd = 0; rd < 4; rd++) {
        int sh = 24 - rd * 8;
#pragma unroll
        for (int h = 0; h < TR; h++) ((unsigned*)hist)[tid + h * 256] = 0;
        __syncthreads();
#pragma unroll
        for (int r = 0; r < TR; r++) {
            unsigned pr = s_prefix[r];
#pragma unroll
            for (int q = 0; q < Nq / 256; q++) {
                unsigned u = __float_as_uint(Dsm[r][tid + q * 256]);
                if ((u & pmask) == pr) atomicAdd(&hist[r][(u >> sh) & 255u], 1u);
            }
        }
        __syncthreads();
        if (warp < TR) {  // warp r scans row r's 256 bins
            int r = warp;
            int base = lane * 8;
            unsigned cnts[8];
            unsigned p = 0;
#pragma unroll
            for (int q2 = 0; q2 < 8; q2++) { cnts[q2] = hist[r][base + q2]; p += cnts[q2]; }
            unsigned incl = p;
            for (int o = 1; o < 32; o <<= 1) {
                unsigned v = __shfl_up_sync(~0u, incl, o);
                if (lane >= o) incl += v;
            }
            unsigned excl = incl - p;
            int rk = s_rank[r];
            __syncwarp();
            if ((int)excl < rk && rk <= (int)incl) {
                int rr = rk - (int)excl;
#pragma unroll
                for (int q2 = 0; q2 < 8; q2++) {
                    if (rr <= (int)cnts[q2]) {
                        s_prefix[r] |= (unsigned)(base + q2) << sh;
                        s_rank[r] = rr;
                        break;
                    }
                    rr -= (int)cnts[q2];
                }
            }
        }
        __syncthreads();
        pmask |= 0xFFu << sh;
    }

    // Gather: keys with s < distpre selected outright; s == distpre marked in
    // the per-row bitmap for index tie-break.
    unsigned distpre[TR];
    int quota[TR];
#pragma unroll
    for (int r = 0; r < TR; r++) { distpre[r] = s_prefix[r]; quota[r] = s_rank[r]; }
#pragma unroll
    for (int r = 0; r < TR; r++) {
#pragma unroll
        for (int q = 0; q < Nq / 256; q++) {
            int j = tid + q * 256;
            unsigned u = __float_as_uint(Dsm[r][j]);
            if (u < distpre[r]) {
                int pos = atomicAdd(&s_cnt[r], 1);
                cand[r][pos] = ((unsigned long long)u << 32) | (unsigned)j;
            } else if (u == distpre[r]) {
                atomicOr(&tiebm[r][j >> 5], 1u << (j & 31));
            }
        }
    }
    __syncthreads();
    if (tid < TR) {
        unsigned acc = 0;
#pragma unroll 1
        for (int w = 0; w < 64; w++) { tiepfx[tid][w] = acc; acc += __popc(tiebm[tid][w]); }
    }
    __syncthreads();
#pragma unroll
    for (int r = 0; r < TR; r++) {
#pragma unroll
        for (int q = 0; q < Nq / 256; q++) {
            int j = tid + q * 256;
            unsigned u = __float_as_uint(Dsm[r][j]);
            if (u == distpre[r]) {
                int rk = (int)tiepfx[r][j >> 5] +
                         __popc(tiebm[r][j >> 5] & ((1u << (j & 31)) - 1u));
                if (rk < quota[r]) {
                    int pos = atomicAdd(&s_cnt[r], 1);
                    if (pos < Kq) cand[r][pos] = ((unsigned long long)u << 32) | (unsigned)j;
                }
            }
        }
    }
    __syncthreads();
    // sqrt only the selected; rerank on (D_bits, j) = reference post-sqrt order
    if (tid < TR * Kq) {
        int r = tid / Kq, k = tid % Kq;
        unsigned long long key = cand[r][k];
        float D = sqrtf(__uint_as_float((unsigned)(key >> 32)));
        cand[r][k] = ((unsigned long long)__float_as_uint(D) << 32) |
                     (key & 0xFFFFFFFFull);
    }
    __syncthreads();
    if (tid < TR * Kq) {
        int r = tid / Kq, k = tid % Kq;
        unsigned long long key = cand[r][k];
        int rk = 0;
#pragma unroll
        for (int s = 0; s < Kq; s++) rk += (cand[r][s] < key);
        int j = (int)(unsigned)(key & 0xFFFFFFFFull);
        outIdx[(size_t)(row0 + r) * Kq + rk] = (float)j;
        outD[(size_t)(row0 + r) * Kq + rk] = __uint_as_float((unsigned)(key >> 32));
    }
}

// ---------------------------------------------------------------------------
// Kernel 3: per-edge features -> output channels + LayerNorm.
// ONE WARP per (b,i); thread owns channels (4c..4c+3) as two packed f32x2
// accumulators. 68 FFMA/edge -> 34 FMA2 + 17 PACK (alu pipe has headroom).
// LN stays a pure shfl_xor reduction.
// ---------------------------------------------------------------------------
__global__ __launch_bounds__(32) void edge_kernel(
    const float* __restrict__ eidx, const float* __restrict__ dnb,
    const int* __restrict__ resi, const int* __restrict__ lig,
    const float* __restrict__ bonds,
    const float* __restrict__ edge_w,
    const float* __restrict__ ln_g, const float* __restrict__ ln_b,
    float* __restrict__ outE) {
    __shared__ __align__(16) float f[Kq][20];  // 16 rbf + tb + pad
    __shared__ int dsm[Kq];

    int lane = threadIdx.x;  // 0..31 -> channels (4*lane .. 4*lane+3)
    int row = blockIdx.x;
    int b = row / Nq, i = row % Nq;
    int c4 = 4 * lane;

    // packed weight pairs: w01 = channels (c4, c4+1), w23 = (c4+2, c4+3)
    unsigned long long w01[17], w23[17];
#pragma unroll
    for (int t = 0; t < 16; t++) {
        float4 wt = *(const float4*)&edge_w[(16 + t) * EC + c4];
        w01[t] = pack2(wt.x, wt.y);
        w23[t] = pack2(wt.z, wt.w);
    }
    {
        float4 wt = *(const float4*)&edge_w[32 * EC + c4];
        w01[16] = pack2(wt.x, wt.y);
        w23[16] = pack2(wt.z, wt.w);
    }
    float4 gg = *(const float4*)&ln_g[c4];
    float4 bb = *(const float4*)&ln_b[c4];

    int ri = resi[row];
    int li = lig[row];
    const float* brow = bonds + ((size_t)b * Nq + i) * Nq;

    // Build feature rows: 32 threads cover 48 edges
    for (int k = lane; k < Kq; k += 32) {
        int j = (int)eidx[(size_t)row * Kq + k];
        float dk = dnb[(size_t)row * Kq + k];
        // chain_labels all-zero in reference => E_chains == 1 always
        int d = ri - resi[b * Nq + j] + 32;
        dsm[k] = max(0, min(64, d));
#pragma unroll
        for (int m = 0; m < 16; m++) {
            float mu = 2.f + (20.f / 15.f) * (float)m;
            float x = (dk - mu) * 0.8f;  // 1/1.25
            f[k][m] = __expf(-x * x);
        }
        f[k][16] = (li | lig[b * Nq + j]) ? brow[j] : 0.f;
        f[k][17] = f[k][18] = f[k][19] = 0.f;
    }
    __syncwarp();

#pragma unroll 1
    for (int k = 0; k < Kq; k++) {
        const float4* fp = (const float4*)f[k];
        float4 C = *(const float4*)&g_C[dsm[k] * EC + c4];
        unsigned long long acc01 = pack2(C.x, C.y);
        unsigned long long acc23 = pack2(C.z, C.w);
#pragma unroll
        for (int q = 0; q < 4; q++) {
            float4 v = fp[q];
            unsigned long long vv;
            vv = pack2(v.x, v.x);
            fma2(acc01, vv, w01[4 * q]);
            fma2(acc23, vv, w23[4 * q]);
            vv = pack2(v.y, v.y);
            fma2(acc01, vv, w01[4 * q + 1]);
            fma2(acc23, vv, w23[4 * q + 1]);
            vv = pack2(v.z, v.z);
            fma2(acc01, vv, w01[4 * q + 2]);
            fma2(acc23, vv, w23[4 * q + 2]);
            vv = pack2(v.w, v.w);
            fma2(acc01, vv, w01[4 * q + 3]);
            fma2(acc23, vv, w23[4 * q + 3]);
        }
        {
            float tb = fp[4].x;
            unsigned long long vv = pack2(tb, tb);
            fma2(acc01, vv, w01[16]);
            fma2(acc23, vv, w23[16]);
        }
        float a0, a1, a2, a3;
        unpack2(acc01, a0, a1);
        unpack2(acc23, a2, a3);
        // LayerNorm across 128 channels: 4 per thread + warp shuffle reduce
        float s = a0 + a1 + a2 + a3;
        float s2 = a0 * a0 + a1 * a1 + a2 * a2 + a3 * a3;
#pragma unroll
        for (int o = 16; o; o >>= 1) {
            s += __shfl_xor_sync(~0u, s, o);
            s2 += __shfl_xor_sync(~0u, s2, o);
        }
        float mean = s * (1.f / EC);
        float var = s2 * (1.f / EC) - mean * mean;
        float rstd = rsqrtf(var + 1e-5f);
        float4 o4;
        o4.x = (a0 - mean) * rstd * gg.x + bb.x;
        o4.y = (a1 - mean) * rstd * gg.y + bb.y;
        o4.z = (a2 - mean) * rstd * gg.z + bb.z;
        o4.w = (a3 - mean) * rstd * gg.w + bb.w;
        *(float4*)&outE[((size_t)row * Kq + k) * EC + c4] = o4;
    }
}

// ---------------------------------------------------------------------------
extern "C" void kernel_launch(void* const* d_in, const int* in_sizes, int n_in,
                              void* d_out, int out_size) {
    const float* coords = (const float*)d_in[0];
    const float* mask   = (const float*)d_in[1];
    const float* bonds  = (const float*)d_in[2];
    const float* pe_w   = (const float*)d_in[3];
    const float* pe_b   = (const float*)d_in[4];
    const float* edge_w = (const float*)d_in[5];
    const float* ln_g   = (const float*)d_in[6];
    const float* ln_b   = (const float*)d_in[7];
    const int* center   = (const int*)d_in[8];
    const int* resi     = (const int*)d_in[9];
    // d_in[10] = asym_id (unused: chain encoding disabled in reference)
    const int* lig      = (const int*)d_in[11];

    float* outE = (float*)d_out;
    size_t nE = (size_t)Bq * Nq * Kq * EC;        // 50,331,648
    float* outIdx = outE + nE;                    // E_idx as float
    float* outD = outIdx + (size_t)Bq * Nq * Kq;  // D_neighbors

    prep_c_kernel<<<66, 128>>>(pe_w, pe_b, edge_w);
    gather_x_kernel<<<(Bq * Nq + 255) / 256, 256>>>(coords, mask, center);
    knn_kernel<<<Bq * Nq / TR, 256>>>(mask, outIdx, outD);
    edge_kernel<<<Bq * Nq, 32>>>(outIdx, outD, resi, lig, bonds, edge_w,
                                 ln_g, ln_b, outE);
}

// round 14
// speedup vs baseline: 1.7316x; 1.0002x over previous
#include <cuda_runtime.h>
#include <math.h>

#define Bq 4
#define Nq 2048
#define Kq 48
#define EC 128
#define TR 4  // rows per KNN block

// Scratch: gathered/masked token center coords, [B*N] as float4
__device__ float4 g_X[Bq * Nq];
// Precomputed positional-encoding contribution: C[d][c] for d in [0,65]
__device__ float g_C[66 * EC];

__device__ __forceinline__ unsigned long long pack2(float a, float b) {
    unsigned long long r;
    asm("mov.b64 %0, {%1, %2};" : "=l"(r) : "f"(a), "f"(b));
    return r;
}
__device__ __forceinline__ void unpack2(unsigned long long v, float& a, float& b) {
    asm("mov.b64 {%0, %1}, %2;" : "=f"(a), "=f"(b) : "l"(v));
}
__device__ __forceinline__ void fma2(unsigned long long& d, unsigned long long a,
                                     unsigned long long b) {
    asm("fma.rn.f32x2 %0, %1, %2, %3;" : "=l"(d) : "l"(a), "l"(b), "l"(d));
}

// ---------------------------------------------------------------------------
// Kernel 0: fold (one_hot(d) @ pe_w + pe_b) @ edge_w[0:16] into a 66x128 LUT
// ---------------------------------------------------------------------------
__global__ void prep_c_kernel(const float* __restrict__ pe_w,
                              const float* __restrict__ pe_b,
                              const float* __restrict__ edge_w) {
    int d = blockIdx.x;
    int c = threadIdx.x;
    float acc = 0.f;
#pragma unroll
    for (int t = 0; t < 16; t++)
        acc += (pe_w[d * 16 + t] + pe_b[t]) * edge_w[t * EC + c];
    g_C[d * EC + c] = acc;
}

// ---------------------------------------------------------------------------
// Kernel 1: gather center-atom coords, apply token mask
// ---------------------------------------------------------------------------
__global__ void gather_x_kernel(const float* __restrict__ coords,
                                const float* __restrict__ mask,
                                const int* __restrict__ center) {
    int t = blockIdx.x * blockDim.x + threadIdx.x;
    if (t >= Bq * Nq) return;
    int b = t / Nq;
    int c = center[t];
    float m = mask[t];
    const float* p = coords + ((size_t)b * Nq + c) * 3;
    g_X[t] = make_float4(p[0] * m, p[1] * m, p[2] * m, 0.f);
}

// ---------------------------------------------------------------------------
// Kernel 2: masked top-K, squared-distance domain, 4 ROWS PER BLOCK.
// (R10/R11 version, unchanged.)
// ---------------------------------------------------------------------------
__global__ __launch_bounds__(256) void knn_kernel(const float* __restrict__ mask,
                                                  float* __restrict__ outIdx,
                                                  float* __restrict__ outD) {
    __shared__ float Dsm[TR][Nq];              // squared (adjusted) distances
    __shared__ unsigned hist[TR][256];
    __shared__ float warpred[8][TR];
    __shared__ float s_smax[TR];
    __shared__ unsigned s_prefix[TR];
    __shared__ int s_rank[TR];
    __shared__ int s_cnt[TR];
    __shared__ unsigned long long cand[TR][Kq];
    __shared__ unsigned tiebm[TR][64];
    __shared__ unsigned tiepfx[TR][64];

    int blk = blockIdx.x;
    int row0 = blk * TR;
    int b = row0 / Nq;
    int tid = threadIdx.x;
    int lane = tid & 31, warp = tid >> 5;

    float4 xi[TR];
    float mi[TR];
#pragma unroll
    for (int r = 0; r < TR; r++) { xi[r] = g_X[row0 + r]; mi[r] = mask[row0 + r]; }
    const float* mrow = mask + b * Nq;

    // Pass 1: squared distances for 4 rows per xj load + masked row maxima
    float lmax[TR] = {0.f, 0.f, 0.f, 0.f};
#pragma unroll
    for (int q = 0; q < Nq / 256; q++) {
        int j = tid + q * 256;
        float4 xj = g_X[b * Nq + j];
        float mj = mrow[j];
#pragma unroll
        for (int r = 0; r < TR; r++) {
            float dx = xi[r].x - xj.x, dy = xi[r].y - xj.y, dz = xi[r].z - xj.z;
            float s = dx * dx + dy * dy + dz * dz + 1e-6f;
            Dsm[r][j] = s;
            lmax[r] = fmaxf(lmax[r], (mi[r] * mj != 0.f) ? s : 0.f);
        }
    }
#pragma unroll
    for (int r = 0; r < TR; r++)
        for (int o = 16; o; o >>= 1)
            lmax[r] = fmaxf(lmax[r], __shfl_xor_sync(~0u, lmax[r], o));
    if (lane == 0)
#pragma unroll
        for (int r = 0; r < TR; r++) warpred[warp][r] = lmax[r];
    __syncthreads();
    if (tid < TR) {
        float m = warpred[0][tid];
#pragma unroll
        for (int w = 1; w < 8; w++) m = fmaxf(m, warpred[w][tid]);
        s_smax[tid] = m;
        s_rank[tid] = Kq;
        s_cnt[tid] = 0;
        s_prefix[tid] = 0;
    }
    ((unsigned*)tiebm)[tid] = 0;  // TR*64 = 256 words
    __syncthreads();

    // Masked-adjust pass: masked pairs -> smax (s-domain Dmax).
    {
        float smaxr[TR];
#pragma unroll
        for (int r = 0; r < TR; r++) smaxr[r] = s_smax[r];
#pragma unroll
        for (int q = 0; q < Nq / 256; q++) {
            int j = tid + q * 256;
            float mj = mrow[j];
#pragma unroll
            for (int r = 0; r < TR; r++)
                if (mi[r] * mj == 0.f) Dsm[r][j] = smaxr[r];
        }
    }
    __syncthreads();

    // 4 radix rounds over the 32 squared-distance bits (8-bit digits).
    unsigned pmask = 0;
#pragma unroll 1
    for (int rd = 0; rd < 4; rd++) {
        int sh = 24 - rd * 8;
#pragma unroll
        for (int h = 0; h < TR; h++) ((unsigned*)hist)[tid + h * 256] = 0;
        __syncthreads();
#pragma unroll
        for (int r = 0; r < TR; r++) {
            unsigned pr = s_prefix[r];
#pragma unroll
            for (int q = 0; q < Nq / 256; q++) {
                unsigned u = __float_as_uint(Dsm[r][tid + q * 256]);
                if ((u & pmask) == pr) atomicAdd(&hist[r][(u >> sh) & 255u], 1u);
            }
        }
        __syncthreads();
        if (warp < TR) {  // warp r scans row r's 256 bins
            int r = warp;
            int base = lane * 8;
            unsigned cnts[8];
            unsigned p = 0;
#pragma unroll
            for (int q2 = 0; q2 < 8; q2++) { cnts[q2] = hist[r][base + q2]; p += cnts[q2]; }
            unsigned incl = p;
            for (int o = 1; o < 32; o <<= 1) {
                unsigned v = __shfl_up_sync(~0u, incl, o);
                if (lane >= o) incl += v;
            }
            unsigned excl = incl - p;
            int rk = s_rank[r];
            __syncwarp();
            if ((int)excl < rk && rk <= (int)incl) {
                int rr = rk - (int)excl;
#pragma unroll
                for (int q2 = 0; q2 < 8; q2++) {
                    if (rr <= (int)cnts[q2]) {
                        s_prefix[r] |= (unsigned)(base + q2) << sh;
                        s_rank[r] = rr;
                        break;
                    }
                    rr -= (int)cnts[q2];
                }
            }
        }
        __syncthreads();
        pmask |= 0xFFu << sh;
    }

    // Gather: keys with s < distpre selected outright; s == distpre marked in
    // the per-row bitmap for index tie-break.
    unsigned distpre[TR];
    int quota[TR];
#pragma unroll
    for (int r = 0; r < TR; r++) { distpre[r] = s_prefix[r]; quota[r] = s_rank[r]; }
#pragma unroll
    for (int r = 0; r < TR; r++) {
#pragma unroll
        for (int q = 0; q < Nq / 256; q++) {
            int j = tid + q * 256;
            unsigned u = __float_as_uint(Dsm[r][j]);
            if (u < distpre[r]) {
                int pos = atomicAdd(&s_cnt[r], 1);
                cand[r][pos] = ((unsigned long long)u << 32) | (unsigned)j;
            } else if (u == distpre[r]) {
                atomicOr(&tiebm[r][j >> 5], 1u << (j & 31));
            }
        }
    }
    __syncthreads();
    if (tid < TR) {
        unsigned acc = 0;
#pragma unroll 1
        for (int w = 0; w < 64; w++) { tiepfx[tid][w] = acc; acc += __popc(tiebm[tid][w]); }
    }
    __syncthreads();
#pragma unroll
    for (int r = 0; r < TR; r++) {
#pragma unroll
        for (int q = 0; q < Nq / 256; q++) {
            int j = tid + q * 256;
            unsigned u = __float_as_uint(Dsm[r][j]);
            if (u == distpre[r]) {
                int rk = (int)tiepfx[r][j >> 5] +
                         __popc(tiebm[r][j >> 5] & ((1u << (j & 31)) - 1u));
                if (rk < quota[r]) {
                    int pos = atomicAdd(&s_cnt[r], 1);
                    if (pos < Kq) cand[r][pos] = ((unsigned long long)u << 32) | (unsigned)j;
                }
            }
        }
    }
    __syncthreads();
    // sqrt only the selected; rerank on (D_bits, j) = reference post-sqrt order
    if (tid < TR * Kq) {
        int r = tid / Kq, k = tid % Kq;
        unsigned long long key = cand[r][k];
        float D = sqrtf(__uint_as_float((unsigned)(key >> 32)));
        cand[r][k] = ((unsigned long long)__float_as_uint(D) << 32) |
                     (key & 0xFFFFFFFFull);
    }
    __syncthreads();
    if (tid < TR * Kq) {
        int r = tid / Kq, k = tid % Kq;
        unsigned long long key = cand[r][k];
        int rk = 0;
#pragma unroll
        for (int s = 0; s < Kq; s++) rk += (cand[r][s] < key);
        int j = (int)(unsigned)(key & 0xFFFFFFFFull);
        outIdx[(size_t)(row0 + r) * Kq + rk] = (float)j;
        outD[(size_t)(row0 + r) * Kq + rk] = __uint_as_float((unsigned)(key >> 32));
    }
}

// ---------------------------------------------------------------------------
// Kernel 3: per-edge features -> output channels + LayerNorm.
// ONE WARP per (b,i); thread owns channels (4c..4c+3) as packed f32x2.
// FOUR independent FMA2 chains (a/b split per accumulator) halve the RAW
// dependency critical path that bound R12 (issue was 49.7%).
// ---------------------------------------------------------------------------
__global__ __launch_bounds__(32) void edge_kernel(
    const float* __restrict__ eidx, const float* __restrict__ dnb,
    const int* __restrict__ resi, const int* __restrict__ lig,
    const float* __restrict__ bonds,
    const float* __restrict__ edge_w,
    const float* __restrict__ ln_g, const float* __restrict__ ln_b,
    float* __restrict__ outE) {
    __shared__ __align__(16) float f[Kq][20];  // 16 rbf + tb + pad
    __shared__ int dsm[Kq];

    int lane = threadIdx.x;  // 0..31 -> channels (4*lane .. 4*lane+3)
    int row = blockIdx.x;
    int b = row / Nq, i = row % Nq;
    int c4 = 4 * lane;

    // packed weight pairs: w01 = channels (c4, c4+1), w23 = (c4+2, c4+3)
    unsigned long long w01[17], w23[17];
#pragma unroll
    for (int t = 0; t < 16; t++) {
        float4 wt = *(const float4*)&edge_w[(16 + t) * EC + c4];
        w01[t] = pack2(wt.x, wt.y);
        w23[t] = pack2(wt.z, wt.w);
    }
    {
        float4 wt = *(const float4*)&edge_w[32 * EC + c4];
        w01[16] = pack2(wt.x, wt.y);
        w23[16] = pack2(wt.z, wt.w);
    }
    float4 gg = *(const float4*)&ln_g[c4];
    float4 bb = *(const float4*)&ln_b[c4];

    int ri = resi[row];
    int li = lig[row];
    const float* brow = bonds + ((size_t)b * Nq + i) * Nq;

    // Build feature rows: 32 threads cover 48 edges
    for (int k = lane; k < Kq; k += 32) {
        int j = (int)eidx[(size_t)row * Kq + k];
        float dk = dnb[(size_t)row * Kq + k];
        // chain_labels all-zero in reference => E_chains == 1 always
        int d = ri - resi[b * Nq + j] + 32;
        dsm[k] = max(0, min(64, d));
#pragma unroll
        for (int m = 0; m < 16; m++) {
            float mu = 2.f + (20.f / 15.f) * (float)m;
            float x = (dk - mu) * 0.8f;  // 1/1.25
            f[k][m] = __expf(-x * x);
        }
        f[k][16] = (li | lig[b * Nq + j]) ? brow[j] : 0.f;
        f[k][17] = f[k][18] = f[k][19] = 0.f;
    }
    __syncwarp();

#pragma unroll 1
    for (int k = 0; k < Kq; k++) {
        const float4* fp = (const float4*)f[k];
        float4 C = *(const float4*)&g_C[dsm[k] * EC + c4];
        // four independent chains: terms 0-7+bond in 'a', terms 8-15 in 'b'
        unsigned long long acc01a = pack2(C.x, C.y), acc01b = 0ull;
        unsigned long long acc23a = pack2(C.z, C.w), acc23b = 0ull;
#pragma unroll
        for (int q = 0; q < 2; q++) {
            float4 v = fp[q];
            unsigned long long vv;
            vv = pack2(v.x, v.x);
            fma2(acc01a, vv, w01[4 * q]);
            fma2(acc23a, vv, w23[4 * q]);
            vv = pack2(v.y, v.y);
            fma2(acc01a, vv, w01[4 * q + 1]);
            fma2(acc23a, vv, w23[4 * q + 1]);
            vv = pack2(v.z, v.z);
            fma2(acc01a, vv, w01[4 * q + 2]);
            fma2(acc23a, vv, w23[4 * q + 2]);
            vv = pack2(v.w, v.w);
            fma2(acc01a, vv, w01[4 * q + 3]);
            fma2(acc23a, vv, w23[4 * q + 3]);
        }
#pragma unroll
        for (int q = 2; q < 4; q++) {
            float4 v = fp[q];
            unsigned long long vv;
            vv = pack2(v.x, v.x);
            fma2(acc01b, vv, w01[4 * q]);
            fma2(acc23b, vv, w23[4 * q]);
            vv = pack2(v.y, v.y);
            fma2(acc01b, vv, w01[4 * q + 1]);
            fma2(acc23b, vv, w23[4 * q + 1]);
            vv = pack2(v.z, v.z);
            fma2(acc01b, vv, w01[4 * q + 2]);
            fma2(acc23b, vv, w23[4 * q + 2]);
            vv = pack2(v.w, v.w);
            fma2(acc01b, vv, w01[4 * q + 3]);
            fma2(acc23b, vv, w23[4 * q + 3]);
        }
        {
            float tb = fp[4].x;
            unsigned long long vv = pack2(tb, tb);
            fma2(acc01a, vv, w01[16]);
            fma2(acc23a, vv, w23[16]);
        }
        float a0, a1, a2, a3, t0, t1, t2, t3;
        unpack2(acc01a, a0, a1);
        unpack2(acc23a, a2, a3);
        unpack2(acc01b, t0, t1);
        unpack2(acc23b, t2, t3);
        a0 += t0; a1 += t1; a2 += t2; a3 += t3;
        // LayerNorm across 128 channels: 4 per thread + warp shuffle reduce
        float s = a0 + a1 + a2 + a3;
        float s2 = a0 * a0 + a1 * a1 + a2 * a2 + a3 * a3;
#pragma unroll
        for (int o = 16; o; o >>= 1) {
            s += __shfl_xor_sync(~0u, s, o);
            s2 += __shfl_xor_sync(~0u, s2, o);
        }
        float mean = s * (1.f / EC);
        float var = s2 * (1.f / EC) - mean * mean;
        float rstd = rsqrtf(var + 1e-5f);
        float4 o4;
        o4.x = (a0 - mean) * rstd * gg.x + bb.x;
        o4.y = (a1 - mean) * rstd * gg.y + bb.y;
        o4.z = (a2 - mean) * rstd * gg.z + bb.z;
        o4.w = (a3 - mean) * rstd * gg.w + bb.w;
        *(float4*)&outE[((size_t)row * Kq + k) * EC + c4] = o4;
    }
}

// ---------------------------------------------------------------------------
extern "C" void kernel_launch(void* const* d_in, const int* in_sizes, int n_in,
                              void* d_out, int out_size) {
    const float* coords = (const float*)d_in[0];
    const float* mask   = (const float*)d_in[1];
    const float* bonds  = (const float*)d_in[2];
    const float* pe_w   = (const float*)d_in[3];
    const float* pe_b   = (const float*)d_in[4];
    const float* edge_w = (const float*)d_in[5];
    const float* ln_g   = (const float*)d_in[6];
    const float* ln_b   = (const float*)d_in[7];
    const int* center   = (const int*)d_in[8];
    const int* resi     = (const int*)d_in[9];
    // d_in[10] = asym_id (unused: chain encoding disabled in reference)
    const int* lig      = (const int*)d_in[11];

    float* outE = (float*)d_out;
    size_t nE = (size_t)Bq * Nq * Kq * EC;        // 50,331,648
    float* outIdx = outE + nE;                    // E_idx as float
    float* outD = outIdx + (size_t)Bq * Nq * Kq;  // D_neighbors

    prep_c_kernel<<<66, 128>>>(pe_w, pe_b, edge_w);
    gather_x_kernel<<<(Bq * Nq + 255) / 256, 256>>>(coords, mask, center);
    knn_kernel<<<Bq * Nq / TR, 256>>>(mask, outIdx, outD);
    edge_kernel<<<Bq * Nq, 32>>>(outIdx, outD, resi, lig, bonds, edge_w,
                                 ln_g, ln_b, outE);
}

// round 17
// speedup vs baseline: 1.8996x; 1.0970x over previous
#include <cuda_runtime.h>
#include <math.h>

#define Bq 4
#define Nq 2048
#define Kq 48
#define EC 128
#define TR 4  // rows per KNN block

// Scratch: gathered/masked token center coords, [B*N] as float4
__device__ float4 g_X[Bq * Nq];
// Precomputed positional-encoding contribution: C[d][c] for d in [0,65]
__device__ float g_C[66 * EC];

__device__ __forceinline__ unsigned long long pack2(float a, float b) {
    unsigned long long r;
    asm("mov.b64 %0, {%1, %2};" : "=l"(r) : "f"(a), "f"(b));
    return r;
}
__device__ __forceinline__ void unpack2(unsigned long long v, float& a, float& b) {
    asm("mov.b64 {%0, %1}, %2;" : "=f"(a), "=f"(b) : "l"(v));
}
__device__ __forceinline__ void fma2(unsigned long long& d, unsigned long long a,
                                     unsigned long long b) {
    asm("fma.rn.f32x2 %0, %1, %2, %3;" : "=l"(d) : "l"(a), "l"(b), "l"(d));
}

// ---------------------------------------------------------------------------
// Kernel 0: fold (one_hot(d) @ pe_w + pe_b) @ edge_w[0:16] into a 66x128 LUT
// ---------------------------------------------------------------------------
__global__ void prep_c_kernel(const float* __restrict__ pe_w,
                              const float* __restrict__ pe_b,
                              const float* __restrict__ edge_w) {
    int d = blockIdx.x;
    int c = threadIdx.x;
    float acc = 0.f;
#pragma unroll
    for (int t = 0; t < 16; t++)
        acc += (pe_w[d * 16 + t] + pe_b[t]) * edge_w[t * EC + c];
    g_C[d * EC + c] = acc;
}

// ---------------------------------------------------------------------------
// Kernel 1: gather center-atom coords, apply token mask
// ---------------------------------------------------------------------------
__global__ void gather_x_kernel(const float* __restrict__ coords,
                                const float* __restrict__ mask,
                                const int* __restrict__ center) {
    int t = blockIdx.x * blockDim.x + threadIdx.x;
    if (t >= Bq * Nq) return;
    int b = t / Nq;
    int c = center[t];
    float m = mask[t];
    const float* p = coords + ((size_t)b * Nq + c) * 3;
    g_X[t] = make_float4(p[0] * m, p[1] * m, p[2] * m, 0.f);
}

// ---------------------------------------------------------------------------
// Kernel 2: masked top-K, squared-distance domain, 4 ROWS PER BLOCK.
// (R10/R11 version, unchanged.)
// ---------------------------------------------------------------------------
__global__ __launch_bounds__(256) void knn_kernel(const float* __restrict__ mask,
                                                  float* __restrict__ outIdx,
                                                  float* __restrict__ outD) {
    __shared__ float Dsm[TR][Nq];              // squared (adjusted) distances
    __shared__ unsigned hist[TR][256];
    __shared__ float warpred[8][TR];
    __shared__ float s_smax[TR];
    __shared__ unsigned s_prefix[TR];
    __shared__ int s_rank[TR];
    __shared__ int s_cnt[TR];
    __shared__ unsigned long long cand[TR][Kq];
    __shared__ unsigned tiebm[TR][64];
    __shared__ unsigned tiepfx[TR][64];

    int blk = blockIdx.x;
    int row0 = blk * TR;
    int b = row0 / Nq;
    int tid = threadIdx.x;
    int lane = tid & 31, warp = tid >> 5;

    float4 xi[TR];
    float mi[TR];
#pragma unroll
    for (int r = 0; r < TR; r++) { xi[r] = g_X[row0 + r]; mi[r] = mask[row0 + r]; }
    const float* mrow = mask + b * Nq;

    // Pass 1: squared distances for 4 rows per xj load + masked row maxima
    float lmax[TR] = {0.f, 0.f, 0.f, 0.f};
#pragma unroll
    for (int q = 0; q < Nq / 256; q++) {
        int j = tid + q * 256;
        float4 xj = g_X[b * Nq + j];
        float mj = mrow[j];
#pragma unroll
        for (int r = 0; r < TR; r++) {
            float dx = xi[r].x - xj.x, dy = xi[r].y - xj.y, dz = xi[r].z - xj.z;
            float s = dx * dx + dy * dy + dz * dz + 1e-6f;
            Dsm[r][j] = s;
            lmax[r] = fmaxf(lmax[r], (mi[r] * mj != 0.f) ? s : 0.f);
        }
    }
#pragma unroll
    for (int r = 0; r < TR; r++)
        for (int o = 16; o; o >>= 1)
            lmax[r] = fmaxf(lmax[r], __shfl_xor_sync(~0u, lmax[r], o));
    if (lane == 0)
#pragma unroll
        for (int r = 0; r < TR; r++) warpred[warp][r] = lmax[r];
    __syncthreads();
    if (tid < TR) {
        float m = warpred[0][tid];
#pragma unroll
        for (int w = 1; w < 8; w++) m = fmaxf(m, warpred[w][tid]);
        s_smax[tid] = m;
        s_rank[tid] = Kq;
        s_cnt[tid] = 0;
        s_prefix[tid] = 0;
    }
    ((unsigned*)tiebm)[tid] = 0;  // TR*64 = 256 words
    __syncthreads();

    // Masked-adjust pass: masked pairs -> smax (s-domain Dmax).
    {
        float smaxr[TR];
#pragma unroll
        for (int r = 0; r < TR; r++) smaxr[r] = s_smax[r];
#pragma unroll
        for (int q = 0; q < Nq / 256; q++) {
            int j = tid + q * 256;
            float mj = mrow[j];
#pragma unroll
            for (int r = 0; r < TR; r++)
                if (mi[r] * mj == 0.f) Dsm[r][j] = smaxr[r];
        }
    }
    __syncthreads();

    // 4 radix rounds over the 32 squared-distance bits (8-bit digits).
    unsigned pmask = 0;
#pragma unroll 1
    for (int rd = 0; rd < 4; rd++) {
        int sh = 24 - rd * 8;
#pragma unroll
        for (int h = 0; h < TR; h++) ((unsigned*)hist)[tid + h * 256] = 0;
        __syncthreads();
#pragma unroll
        for (int r = 0; r < TR; r++) {
            unsigned pr = s_prefix[r];
#pragma unroll
            for (int q = 0; q < Nq / 256; q++) {
                unsigned u = __float_as_uint(Dsm[r][tid + q * 256]);
                if ((u & pmask) == pr) atomicAdd(&hist[r][(u >> sh) & 255u], 1u);
            }
        }
        __syncthreads();
        if (warp < TR) {  // warp r scans row r's 256 bins
            int r = warp;
            int base = lane * 8;
            unsigned cnts[8];
            unsigned p = 0;
#pragma unroll
            for (int q2 = 0; q2 < 8; q2++) { cnts[q2] = hist[r][base + q2]; p += cnts[q2]; }
            unsigned incl = p;
            for (int o = 1; o < 32; o <<= 1) {
                unsigned v = __shfl_up_sync(~0u, incl, o);
                if (lane >= o) incl += v;
            }
            unsigned excl = incl - p;
            int rk = s_rank[r];
            __syncwarp();
            if ((int)excl < rk && rk <= (int)incl) {
                int rr = rk - (int)excl;
#pragma unroll
                for (int q2 = 0; q2 < 8; q2++) {
                    if (rr <= (int)cnts[q2]) {
                        s_prefix[r] |= (unsigned)(base + q2) << sh;
                        s_rank[r] = rr;
                        break;
                    }
                    rr -= (int)cnts[q2];
                }
            }
        }
        __syncthreads();
        pmask |= 0xFFu << sh;
    }

    // Gather: keys with s < distpre selected outright; s == distpre marked in
    // the per-row bitmap for index tie-break.
    unsigned distpre[TR];
    int quota[TR];
#pragma unroll
    for (int r = 0; r < TR; r++) { distpre[r] = s_prefix[r]; quota[r] = s_rank[r]; }
#pragma unroll
    for (int r = 0; r < TR; r++) {
#pragma unroll
        for (int q = 0; q < Nq / 256; q++) {
            int j = tid + q * 256;
            unsigned u = __float_as_uint(Dsm[r][j]);
            if (u < distpre[r]) {
                int pos = atomicAdd(&s_cnt[r], 1);
                cand[r][pos] = ((unsigned long long)u << 32) | (unsigned)j;
            } else if (u == distpre[r]) {
                atomicOr(&tiebm[r][j >> 5], 1u << (j & 31));
            }
        }
    }
    __syncthreads();
    if (tid < TR) {
        unsigned acc = 0;
#pragma unroll 1
        for (int w = 0; w < 64; w++) { tiepfx[tid][w] = acc; acc += __popc(tiebm[tid][w]); }
    }
    __syncthreads();
#pragma unroll
    for (int r = 0; r < TR; r++) {
#pragma unroll
        for (int q = 0; q < Nq / 256; q++) {
            int j = tid + q * 256;
            unsigned u = __float_as_uint(Dsm[r][j]);
            if (u == distpre[r]) {
                int rk = (int)tiepfx[r][j >> 5] +
                         __popc(tiebm[r][j >> 5] & ((1u << (j & 31)) - 1u));
                if (rk < quota[r]) {
                    int pos = atomicAdd(&s_cnt[r], 1);
                    if (pos < Kq) cand[r][pos] = ((unsigned long long)u << 32) | (unsigned)j;
                }
            }
        }
    }
    __syncthreads();
    // sqrt only the selected; rerank on (D_bits, j) = reference post-sqrt order
    if (tid < TR * Kq) {
        int r = tid / Kq, k = tid % Kq;
        unsigned long long key = cand[r][k];
        float D = sqrtf(__uint_as_float((unsigned)(key >> 32)));
        cand[r][k] = ((unsigned long long)__float_as_uint(D) << 32) |
                     (key & 0xFFFFFFFFull);
    }
    __syncthreads();
    if (tid < TR * Kq) {
        int r = tid / Kq, k = tid % Kq;
        unsigned long long key = cand[r][k];
        int rk = 0;
#pragma unroll
        for (int s = 0; s < Kq; s++) rk += (cand[r][s] < key);
        int j = (int)(unsigned)(key & 0xFFFFFFFFull);
        outIdx[(size_t)(row0 + r) * Kq + rk] = (float)j;
        outD[(size_t)(row0 + r) * Kq + rk] = __uint_as_float((unsigned)(key >> 32));
    }
}

// ---------------------------------------------------------------------------
// Kernel 3: per-edge features -> output channels + LayerNorm.
// ONE WARP per (b,i); thread owns channels (4c..4c+3) as packed f32x2.
// Mainloop processes 4 EDGES per iteration: the 4 LN shuffle reductions run
// INTERLEAVED (8 independent chains), amortizing the ~130-cycle shuffle
// latency that bound R12-R14 (issue ~52%, nothing saturated).
// ---------------------------------------------------------------------------
__global__ __launch_bounds__(32) void edge_kernel(
    const float* __restrict__ eidx, const float* __restrict__ dnb,
    const int* __restrict__ resi, const int* __restrict__ lig,
    const float* __restrict__ bonds,
    const float* __restrict__ edge_w,
    const float* __restrict__ ln_g, const float* __restrict__ ln_b,
    float* __restrict__ outE) {
    __shared__ __align__(16) float f[Kq][20];  // 16 rbf + tb + pad
    __shared__ int dsm[Kq];

    int lane = threadIdx.x;  // 0..31 -> channels (4*lane .. 4*lane+3)
    int row = blockIdx.x;
    int b = row / Nq, i = row % Nq;
    int c4 = 4 * lane;

    // packed weight pairs: w01 = channels (c4, c4+1), w23 = (c4+2, c4+3)
    unsigned long long w01[17], w23[17];
#pragma unroll
    for (int t = 0; t < 16; t++) {
        float4 wt = *(const float4*)&edge_w[(16 + t) * EC + c4];
        w01[t] = pack2(wt.x, wt.y);
        w23[t] = pack2(wt.z, wt.w);
    }
    {
        float4 wt = *(const float4*)&edge_w[32 * EC + c4];
        w01[16] = pack2(wt.x, wt.y);
        w23[16] = pack2(wt.z, wt.w);
    }
    float4 gg = *(const float4*)&ln_g[c4];
    float4 bb = *(const float4*)&ln_b[c4];

    int ri = resi[row];
    int li = lig[row];
    const float* brow = bonds + ((size_t)b * Nq + i) * Nq;

    // Build feature rows: 32 threads cover 48 edges
    for (int k = lane; k < Kq; k += 32) {
        int j = (int)eidx[(size_t)row * Kq + k];
        float dk = dnb[(size_t)row * Kq + k];
        // chain_labels all-zero in reference => E_chains == 1 always
        int d = ri - resi[b * Nq + j] + 32;
        dsm[k] = max(0, min(64, d));
#pragma unroll
        for (int m = 0; m < 16; m++) {
            float mu = 2.f + (20.f / 15.f) * (float)m;
            float x = (dk - mu) * 0.8f;  // 1/1.25
            f[k][m] = __expf(-x * x);
        }
        f[k][16] = (li | lig[b * Nq + j]) ? brow[j] : 0.f;
        f[k][17] = f[k][18] = f[k][19] = 0.f;
    }
    __syncwarp();

#pragma unroll 1
    for (int k0 = 0; k0 < Kq; k0 += 4) {
        unsigned long long a01[4], a23[4];
        // batch-issue the 4 g_C loads (latency overlapped)
#pragma unroll
        for (int e = 0; e < 4; e++) {
            float4 C = *(const float4*)&g_C[dsm[k0 + e] * EC + c4];
            a01[e] = pack2(C.x, C.y);
            a23[e] = pack2(C.z, C.w);
        }
        // accumulate: 8 independent FMA2 chains across the 4-edge batch
#pragma unroll
        for (int e = 0; e < 4; e++) {
            const float4* fp = (const float4*)f[k0 + e];
#pragma unroll
            for (int q = 0; q < 4; q++) {
                float4 v = fp[q];
                unsigned long long vv;
                vv = pack2(v.x, v.x);
                fma2(a01[e], vv, w01[4 * q]);
                fma2(a23[e], vv, w23[4 * q]);
                vv = pack2(v.y, v.y);
                fma2(a01[e], vv, w01[4 * q + 1]);
                fma2(a23[e], vv, w23[4 * q + 1]);
                vv = pack2(v.z, v.z);
                fma2(a01[e], vv, w01[4 * q + 2]);
                fma2(a23[e], vv, w23[4 * q + 2]);
                vv = pack2(v.w, v.w);
                fma2(a01[e], vv, w01[4 * q + 3]);
                fma2(a23[e], vv, w23[4 * q + 3]);
            }
            float tb = fp[4].x;
            unsigned long long vv = pack2(tb, tb);
            fma2(a01[e], vv, w01[16]);
            fma2(a23[e], vv, w23[16]);
        }
        // LayerNorm for 4 edges with INTERLEAVED shuffle chains
        float a0[4], a1[4], a2[4], a3[4], s[4], s2[4];
#pragma unroll
        for (int e = 0; e < 4; e++) {
            unpack2(a01[e], a0[e], a1[e]);
            unpack2(a23[e], a2[e], a3[e]);
            s[e] = (a0[e] + a1[e]) + (a2[e] + a3[e]);
            s2[e] = (a0[e] * a0[e] + a1[e] * a1[e]) + (a2[e] * a2[e] + a3[e] * a3[e]);
        }
#pragma unroll
        for (int o = 16; o; o >>= 1) {
#pragma unroll
            for (int e = 0; e < 4; e++) {
                s[e] += __shfl_xor_sync(~0u, s[e], o);
                s2[e] += __shfl_xor_sync(~0u, s2[e], o);
            }
        }
#pragma unroll
        for (int e = 0; e < 4; e++) {
            float mean = s[e] * (1.f / EC);
            float var = s2[e] * (1.f / EC) - mean * mean;
            float rstd = rsqrtf(var + 1e-5f);
            float4 o4;
            o4.x = (a0[e] - mean) * rstd * gg.x + bb.x;
            o4.y = (a1[e] - mean) * rstd * gg.y + bb.y;
            o4.z = (a2[e] - mean) * rstd * gg.z + bb.z;
            o4.w = (a3[e] - mean) * rstd * gg.w + bb.w;
            *(float4*)&outE[((size_t)row * Kq + k0 + e) * EC + c4] = o4;
        }
    }
}

// ---------------------------------------------------------------------------
extern "C" void kernel_launch(void* const* d_in, const int* in_sizes, int n_in,
                              void* d_out, int out_size) {
    const float* coords = (const float*)d_in[0];
    const float* mask   = (const float*)d_in[1];
    const float* bonds  = (const float*)d_in[2];
    const float* pe_w   = (const float*)d_in[3];
    const float* pe_b   = (const float*)d_in[4];
    const float* edge_w = (const float*)d_in[5];
    const float* ln_g   = (const float*)d_in[6];
    const float* ln_b   = (const float*)d_in[7];
    const int* center   = (const int*)d_in[8];
    const int* resi     = (const int*)d_in[9];
    // d_in[10] = asym_id (unused: chain encoding disabled in reference)
    const int* lig      = (const int*)d_in[11];

    float* outE = (float*)d_out;
    size_t nE = (size_t)Bq * Nq * Kq * EC;        // 50,331,648
    float* outIdx = outE + nE;                    // E_idx as float
    float* outD = outIdx + (size_t)Bq * Nq * Kq;  // D_neighbors

    prep_c_kernel<<<66, 128>>>(pe_w, pe_b, edge_w);
    gather_x_kernel<<<(Bq * Nq + 255) / 256, 256>>>(coords, mask, center);
    knn_kernel<<<Bq * Nq / TR, 256>>>(mask, outIdx, outD);
    edge_kernel<<<Bq * Nq, 32>>>(outIdx, outD, resi, lig, bonds, edge_w,
                                 ln_g, ln_b, outE);
}